// round 3
// baseline (speedup 1.0000x reference)
#include <cuda_runtime.h>
#include <cuda_fp16.h>

#define BS 64
#define G 360
#define V 100
#define D 32
#define U 512
#define T 15
#define VOC 5000
#define TD 512
#define H 8
#define E 544          // D + U
#define HD 68          // E / H
#define NEG 0.2f
#define INV_S 0.12126781251816648f   // 1/sqrt(68)
#define TI 60          // i-tile rows in fused attention pass
#define NTILE 6        // G / TI
#define XDIM 1056      // E + TD (concat LSTM input incl. recurrent a)
#define R4U 2048       // 4*U

// ----------------------------- device scratch -----------------------------
__device__ float  g_feat[BS*G*D];
__device__ float  g_qf[(size_t)BS*G*E];
__device__ float  g_kf[(size_t)BS*G*E];
__device__ float  g_kfT[(size_t)BS*E*G];
__device__ float  g_A[(size_t)BS*H*G*G];          // 265 MB fp32 scores
__device__ __half g_Ebuf[(size_t)BS*H*G*G];       // 133 MB fp16 exp(A - rowmax)
__device__ float  g_WqaT[U*E];
__device__ float  g_Wcat[(size_t)XDIM*R4U];       // [x][r], x = [ctx(32); emb(512); a(512)]
__device__ float  g_bias[R4U];
__device__ float  g_W1T[U*256];
__device__ float  g_W2T[256*VOC];
__device__ float  g_qa[BS*E];
__device__ float  g_e[BS*H*G];
__device__ float  g_wpart[BS*H*NTILE*G];
__device__ float  g_ctx[BS*D];
__device__ float  g_gates[BS*R4U];
__device__ float  g_a[BS*U];
__device__ float  g_c[BS*U];
__device__ float  g_h1[BS*256];
__device__ float  g_logits[BS*VOC];

__device__ __forceinline__ float sigmoidf_(float x){ return 1.f/(1.f+__expf(-x)); }
__device__ __forceinline__ float leakyf_(float x){ return x > 0.f ? x : NEG*x; }

// ----------------------------- one-time prep ------------------------------
__global__ void k_prep_wqat(const float* __restrict__ in_w){
    int idx = blockIdx.x*256 + threadIdx.x;
    if (idx < U*E){ int u = idx/E, e = idx - u*E; g_WqaT[idx] = in_w[(size_t)e*E + D + u]; }
}
__global__ void k_prep_wcat_ih(const float* __restrict__ Wih){
    int idx = blockIdx.x*256 + threadIdx.x;
    if (idx < E*R4U){ int x = idx/R4U, r = idx - x*R4U; g_Wcat[idx] = Wih[(size_t)r*E + x]; }
}
__global__ void k_prep_wcat_hh(const float* __restrict__ Whh){
    int idx = blockIdx.x*256 + threadIdx.x;
    if (idx < U*R4U){ int u = idx/R4U, r = idx - u*R4U; g_Wcat[(size_t)(E+u)*R4U + r] = Whh[(size_t)r*U + u]; }
}
__global__ void k_prep_w1t(const float* __restrict__ W1){
    int idx = blockIdx.x*256 + threadIdx.x;
    if (idx < U*256){ int u = idx/256, k = idx - u*256; g_W1T[idx] = W1[(size_t)k*U + u]; }
}
__global__ void k_prep_w2t(const float* __restrict__ W2){
    int idx = blockIdx.x*256 + threadIdx.x;
    if (idx < 256*VOC){ int k = idx/VOC, v = idx - k*VOC; g_W2T[idx] = W2[(size_t)v*256 + k]; }
}
__global__ void k_prep_bias(const float* __restrict__ bih, const float* __restrict__ bhh){
    int idx = blockIdx.x*256 + threadIdx.x;
    if (idx < R4U) g_bias[idx] = bih[idx] + bhh[idx];
}
__global__ void k_init_ac(const float* __restrict__ a0, const float* __restrict__ c0){
    int idx = blockIdx.x*256 + threadIdx.x;
    if (idx < BS*U){ g_a[idx] = a0[idx]; g_c[idx] = c0[idx]; }
}

// ---------------------- encoder: feat = lrelu(LN(x@W+b)) -------------------
__global__ void k_encoder(const float* __restrict__ features, const float* __restrict__ enc_W,
                          const float* __restrict__ enc_b, const float* __restrict__ enc_g,
                          const float* __restrict__ enc_beta){
    int bg = blockIdx.x; int b = bg / G, g = bg - b*G;
    int d = threadIdx.x;                   // 0..31, one warp
    __shared__ float xs[V];
    for (int v = d; v < V; v += 32) xs[v] = features[(size_t)b*(G*V) + (size_t)g*V + v];
    __syncwarp();
    const float* w = enc_W + ((size_t)g*D + d)*V;
    float acc = enc_b[g*D + d];
    #pragma unroll 4
    for (int v = 0; v < V; v++) acc += xs[v]*w[v];
    float m = acc;
    #pragma unroll
    for (int o=16;o;o>>=1) m += __shfl_xor_sync(0xffffffffu, m, o);
    m *= (1.f/32.f);
    float dv = acc - m;
    float vv = dv*dv;
    #pragma unroll
    for (int o=16;o;o>>=1) vv += __shfl_xor_sync(0xffffffffu, vv, o);
    vv *= (1.f/32.f);
    float y = dv * rsqrtf(vv + 1e-5f) * enc_g[d] + enc_beta[d];
    g_feat[(size_t)bg*D + d] = leakyf_(y);
}

// ---------------------- qf / kf projections (K = 32) ----------------------
__global__ void k_qkf(const float* __restrict__ in_w, const float* __restrict__ in_b){
    int mat = blockIdx.y >> 1;             // 0=q, 1=k
    int eh  = blockIdx.y & 1;              // e-half
    int le  = threadIdx.x;                 // 0..271
    int ebase = eh*272;
    __shared__ float Ws[272*33];
    __shared__ float fs[D];
    for (int k = le; k < 272*D; k += 272){
        int i = k >> 5, d = k & 31;
        Ws[i*33 + d] = in_w[((size_t)(mat*E + ebase + i))*E + d];
    }
    // kf gets bk folded in? No: bk cancels in softmax; qf gets no bias (bq is in qa).
    __syncthreads();
    int r0 = blockIdx.x * 96;
    for (int rr = 0; rr < 96; rr++){
        int row = r0 + rr;
        if (le < D) fs[le] = g_feat[(size_t)row*D + le];
        __syncthreads();
        float acc = 0.f;
        #pragma unroll
        for (int d = 0; d < D; d++) acc += fs[d]*Ws[le*33 + d];
        if (mat == 0) g_qf[(size_t)row*E + ebase + le] = acc;
        else          g_kf[(size_t)row*E + ebase + le] = acc;
        __syncthreads();
    }
    (void)in_b;
}

// ---------------------- transpose kf -> kfT[b][e][g] -----------------------
__global__ void k_trkf(){
    __shared__ float tile[32][33];
    int b = blockIdx.z;
    int g0 = blockIdx.x*32, e0 = blockIdx.y*32;
    int tx = threadIdx.x, ty = threadIdx.y;         // 32 x 8
    for (int i = ty; i < 32; i += 8){
        int g = g0 + i, e = e0 + tx;
        if (g < G && e < E) tile[i][tx] = g_kf[((size_t)b*G + g)*E + e];
    }
    __syncthreads();
    for (int i = ty; i < 32; i += 8){
        int e = e0 + i, g = g0 + tx;
        if (e < E && g < G) g_kfT[((size_t)b*E + e)*G + g] = tile[tx][i];
    }
}

// ---------------------- A[b,h,i,j] = qf.kf / sqrt(HD) ----------------------
__global__ void k_agemm(){
    int bh = blockIdx.z; int b = bh >> 3, h = bh & 7;
    int i0 = blockIdx.y << 6, j0 = blockIdx.x << 6;
    __shared__ float Qs[HD*68];        // [d][ii]
    __shared__ float Ks[HD*68];        // [d][jj]
    int tid = threadIdx.x;             // 256
    const float* qbase = g_qf + (size_t)(b*G)*E + h*HD;
    for (int k = tid; k < 64*HD; k += 256){
        int ii = k / HD, d = k - ii*HD;
        int gi = i0 + ii;
        Qs[d*68 + ii] = (gi < G) ? qbase[(size_t)gi*E + d] : 0.f;
    }
    const float* kbase = g_kfT + ((size_t)b*E + h*HD)*G;
    for (int k = tid; k < 64*HD; k += 256){
        int d = k >> 6, jj = k & 63;
        int gj = j0 + jj;
        Ks[d*68 + jj] = (gj < G) ? kbase[(size_t)d*G + gj] : 0.f;
    }
    __syncthreads();
    int tx = tid & 15, ty = tid >> 4;
    float acc[4][4] = {};
    #pragma unroll 4
    for (int d = 0; d < HD; d++){
        float4 q4 = *(const float4*)&Qs[d*68 + (ty<<2)];
        float4 k4 = *(const float4*)&Ks[d*68 + (tx<<2)];
        float qr[4] = {q4.x,q4.y,q4.z,q4.w};
        float kr[4] = {k4.x,k4.y,k4.z,k4.w};
        #pragma unroll
        for (int r = 0; r < 4; r++)
            #pragma unroll
            for (int c = 0; c < 4; c++) acc[r][c] += qr[r]*kr[c];
    }
    float* Ab = g_A + (size_t)bh*G*G;
    #pragma unroll
    for (int r = 0; r < 4; r++){
        int i = i0 + (ty<<2) + r;
        if (i >= G) continue;
        #pragma unroll
        for (int c = 0; c < 4; c++){
            int j = j0 + (tx<<2) + c;
            if (j < G) Ab[(size_t)i*G + j] = acc[r][c]*INV_S;
        }
    }
}

// -------------------- E = exp(A - rowmax) -> fp16 ---------------------------
__global__ void k_expE(){
    int row  = blockIdx.x*8 + (threadIdx.x >> 5);     // row in [0, BS*H*G)
    int lane = threadIdx.x & 31;
    const float* Arow = g_A + (size_t)row*G;
    float m = -1e30f;
    for (int j = lane; j < G; j += 32) m = fmaxf(m, Arow[j]);
    #pragma unroll
    for (int o=16;o;o>>=1) m = fmaxf(m, __shfl_xor_sync(0xffffffffu, m, o));
    __half* Erow = g_Ebuf + (size_t)row*G;
    for (int j = lane; j < G; j += 32) Erow[j] = __float2half(__expf(Arow[j] - m));
}

// ----------------------- per-step: qa = Wqa @ a + bq -----------------------
__global__ void k_qa(const float* __restrict__ in_b){
    int b = blockIdx.x, e = threadIdx.x;    // 544 threads
    __shared__ float as[U];
    if (e < U) as[e] = g_a[b*U + e];
    __syncthreads();
    float acc0 = in_b[e], acc1 = 0.f;
    #pragma unroll 4
    for (int u = 0; u < U; u += 2){
        acc0 += as[u]  *g_WqaT[(size_t)u*E + e];
        acc1 += as[u+1]*g_WqaT[(size_t)(u+1)*E + e];
    }
    g_qa[b*E + e] = acc0 + acc1;
}

// ------------------ per-step: v_j = qa.kf_j; e = exp(v - max) --------------
__global__ void k_ve(){
    int bh = blockIdx.x; int b = bh >> 3, h = bh & 7;
    int j = threadIdx.x;                     // 384 threads
    __shared__ float qs[HD];
    __shared__ float wred[12];
    if (j < HD) qs[j] = g_qa[b*E + h*HD + j];
    __syncthreads();
    float v = -1e30f;
    if (j < G){
        const float* kcol = g_kfT + ((size_t)b*E + h*HD)*G + j;
        float acc = 0.f;
        #pragma unroll 4
        for (int d = 0; d < HD; d++) acc += qs[d]*kcol[(size_t)d*G];
        v = acc * INV_S;
    }
    float m = v;
    #pragma unroll
    for (int o=16;o;o>>=1) m = fmaxf(m, __shfl_xor_sync(0xffffffffu, m, o));
    int warp = j >> 5, lane = j & 31;
    if (lane == 0) wred[warp] = m;
    __syncthreads();
    if (j == 0){
        float mm = wred[0];
        #pragma unroll
        for (int i = 1; i < 12; i++) mm = fmaxf(mm, wred[i]);
        wred[0] = mm;
    }
    __syncthreads();
    if (j < G) g_e[bh*G + j] = __expf(v - wred[0]);
}

// -------- per-step fused attention: single pass over E per step -----------
__global__ void k_attn(){
    int blk = blockIdx.x;                        // BS*H*NTILE
    int bh = blk / NTILE; int tile = blk - bh*NTILE;
    int i0 = tile*TI;
    __shared__ __half Es[TI*G];                  // 43.2 KB
    __shared__ float  es[G];
    __shared__ float  rs[TI];
    int tid = threadIdx.x;                       // 384
    for (int j = tid; j < G; j += 384) es[j] = g_e[bh*G + j];
    {
        const uint4* s4 = (const uint4*)(g_Ebuf + ((size_t)bh*G + i0)*G);
        uint4* d4 = (uint4*)Es;
        for (int k = tid; k < TI*G/8; k += 384) d4[k] = s4[k];
    }
    __syncthreads();
    int warp = tid >> 5, lane = tid & 31;
    for (int i = warp; i < TI; i += 12){
        const __half* er = Es + i*G;
        float acc = 0.f;
        for (int j = lane; j < G; j += 32) acc += __half2float(er[j])*es[j];
        #pragma unroll
        for (int o=16;o;o>>=1) acc += __shfl_xor_sync(0xffffffffu, acc, o);
        if (lane == 0) rs[i] = 1.f/acc;
    }
    __syncthreads();
    if (tid < G){
        float a0 = 0.f, a1 = 0.f;
        #pragma unroll 10
        for (int i = 0; i < TI; i += 2){
            a0 += __half2float(Es[i*G + tid])    *rs[i];
            a1 += __half2float(Es[(i+1)*G + tid])*rs[i+1];
        }
        g_wpart[(size_t)blk*G + tid] = es[tid]*(a0 + a1);
    }
}

// ------------- per-step: w reduce + attention output + ctx ----------------
__global__ void k_ctx(float* __restrict__ out, int t){
    int b = blockIdx.x, tid = threadIdx.x;       // 384
    __shared__ float ws[G];
    if (tid < G){
        float acc = 0.f;
        const float* p = g_wpart + (size_t)b*H*NTILE*G + tid;
        #pragma unroll
        for (int k = 0; k < H*NTILE; k++) acc += p[(size_t)k*G];
        acc *= (1.f/(float)(H*G));
        ws[tid] = acc;
        out[(size_t)BS*T*VOC + ((size_t)b*T + t)*G + tid] = acc;
    }
    __syncthreads();
    if (tid < D){
        float acc = 0.f;
        for (int j = 0; j < G; j++) acc += ws[j]*g_feat[(size_t)(b*G + j)*D + tid];
        g_ctx[b*D + tid] = acc;
    }
}

// ------------- per-step LSTM gate GEMM: 64 x 2048 x 1056 -------------------
__global__ void k_gates(const int* __restrict__ text, const float* __restrict__ emb, int t){
    int r  = blockIdx.x*256 + threadIdx.x;       // gridDim.x = 8
    int b0 = blockIdx.y*8;                       // gridDim.y = 8
    int tid = threadIdx.x;
    __shared__ float xs[8][XDIM];
    for (int bb = 0; bb < 8; bb++){
        int b = b0 + bb;
        if (tid < D) xs[bb][tid] = g_ctx[b*D + tid];
        int tok = text[b*T + t];
        for (int x = tid; x < TD; x += 256) xs[bb][D + x] = emb[(size_t)tok*TD + x];
        for (int u = tid; u < U; u += 256)  xs[bb][E + u] = g_a[b*U + u];
    }
    __syncthreads();
    float acc[8] = {};
    for (int x = 0; x < XDIM; x++){
        float w = g_Wcat[(size_t)x*R4U + r];
        #pragma unroll
        for (int bb = 0; bb < 8; bb++) acc[bb] += xs[bb][x]*w;
    }
    float bsv = g_bias[r];
    #pragma unroll
    for (int bb = 0; bb < 8; bb++) g_gates[(size_t)(b0+bb)*R4U + r] = acc[bb] + bsv;
}

// ------------- per-step LSTM cell + layernorm -> a --------------------------
__global__ void k_lstm(const float* __restrict__ ln_g, const float* __restrict__ ln_b){
    int b = blockIdx.x, u = threadIdx.x;         // 512
    const float* gr = g_gates + (size_t)b*R4U;
    float c = sigmoidf_(gr[U + u])*g_c[b*U + u] + sigmoidf_(gr[u])*tanhf(gr[2*U + u]);
    g_c[b*U + u] = c;
    float h = sigmoidf_(gr[3*U + u])*tanhf(c);
    float s1 = h, s2 = h*h;
    #pragma unroll
    for (int o=16;o;o>>=1){
        s1 += __shfl_xor_sync(0xffffffffu, s1, o);
        s2 += __shfl_xor_sync(0xffffffffu, s2, o);
    }
    __shared__ float r1[16], r2[16];
    int w = u >> 5, l = u & 31;
    if (l == 0){ r1[w] = s1; r2[w] = s2; }
    __syncthreads();
    if (u == 0){
        float t1 = 0.f, t2 = 0.f;
        #pragma unroll
        for (int i = 0; i < 16; i++){ t1 += r1[i]; t2 += r2[i]; }
        r1[0] = t1; r2[0] = t2;
    }
    __syncthreads();
    float m  = r1[0]*(1.f/(float)U);
    float e2 = r2[0]*(1.f/(float)U);
    float var = e2 - m*m;
    g_a[b*U + u] = (h - m)*rsqrtf(var + 1e-5f)*ln_g[u] + ln_b[u];
}

// ------------- per-step MLP layer 1 ----------------------------------------
__global__ void k_mlp1(const float* __restrict__ b1){
    int b = blockIdx.x, k = threadIdx.x;         // 256
    __shared__ float ss[U];
    for (int u = k; u < U; u += 256) ss[u] = leakyf_(g_a[b*U + u]);
    __syncthreads();
    float acc = b1[k];
    #pragma unroll 8
    for (int u = 0; u < U; u++) acc += ss[u]*g_W1T[(size_t)u*256 + k];
    g_h1[b*256 + k] = leakyf_(acc);
}

// ------------- per-step MLP layer 2 + softmax -> output --------------------
__global__ void k_mlp2(const float* __restrict__ b2, float* __restrict__ out, int t){
    int b = blockIdx.x, tid = threadIdx.x;       // 512
    __shared__ float hs[256];
    __shared__ float red[16];
    if (tid < 256) hs[tid] = g_h1[b*256 + tid];
    __syncthreads();
    float lmax = -1e30f;
    for (int v = tid; v < VOC; v += 512){
        float acc = b2[v];
        #pragma unroll 8
        for (int k = 0; k < 256; k++) acc += hs[k]*g_W2T[(size_t)k*VOC + v];
        g_logits[b*VOC + v] = acc;
        lmax = fmaxf(lmax, acc);
    }
    #pragma unroll
    for (int o=16;o;o>>=1) lmax = fmaxf(lmax, __shfl_xor_sync(0xffffffffu, lmax, o));
    if ((tid & 31) == 0) red[tid >> 5] = lmax;
    __syncthreads();
    if (tid == 0){
        float m = red[0];
        #pragma unroll
        for (int i = 1; i < 16; i++) m = fmaxf(m, red[i]);
        red[0] = m;
    }
    __syncthreads();
    float m = red[0];
    __syncthreads();
    float lsum = 0.f;
    for (int v = tid; v < VOC; v += 512) lsum += __expf(g_logits[b*VOC + v] - m);
    #pragma unroll
    for (int o=16;o;o>>=1) lsum += __shfl_xor_sync(0xffffffffu, lsum, o);
    if ((tid & 31) == 0) red[tid >> 5] = lsum;
    __syncthreads();
    if (tid == 0){
        float s = 0.f;
        #pragma unroll
        for (int i = 0; i < 16; i++) s += red[i];
        red[0] = 1.f/s;
    }
    __syncthreads();
    float inv = red[0];
    float* orow = out + ((size_t)b*T + t)*VOC;
    for (int v = tid; v < VOC; v += 512) orow[v] = __expf(g_logits[b*VOC + v] - m)*inv;
}

// ---------------------------------------------------------------------------
extern "C" void kernel_launch(void* const* d_in, const int* in_sizes, int n_in,
                              void* d_out, int out_size){
    const float* features = (const float*)d_in[0];
    const int*   text     = (const int*)  d_in[1];
    const float* a0       = (const float*)d_in[2];
    const float* c0       = (const float*)d_in[3];
    const float* enc_W    = (const float*)d_in[4];
    const float* enc_b    = (const float*)d_in[5];
    const float* enc_g    = (const float*)d_in[6];
    const float* enc_beta = (const float*)d_in[7];
    const float* emb      = (const float*)d_in[8];
    const float* in_w     = (const float*)d_in[9];
    const float* in_b     = (const float*)d_in[10];
    const float* Wih      = (const float*)d_in[11];
    const float* Whh      = (const float*)d_in[12];
    const float* bih      = (const float*)d_in[13];
    const float* bhh      = (const float*)d_in[14];
    const float* ln_g     = (const float*)d_in[15];
    const float* ln_b     = (const float*)d_in[16];
    const float* W1       = (const float*)d_in[17];
    const float* b1       = (const float*)d_in[18];
    const float* W2       = (const float*)d_in[19];
    const float* b2       = (const float*)d_in[20];
    float* out = (float*)d_out;
    (void)in_sizes; (void)n_in; (void)out_size;

    // ---- one-time prep ----
    k_prep_wqat   <<<(U*E + 255)/256, 256>>>(in_w);
    k_prep_wcat_ih<<<(E*R4U + 255)/256, 256>>>(Wih);
    k_prep_wcat_hh<<<(U*R4U + 255)/256, 256>>>(Whh);
    k_prep_w1t    <<<(U*256 + 255)/256, 256>>>(W1);
    k_prep_w2t    <<<(256*VOC + 255)/256, 256>>>(W2);
    k_prep_bias   <<<(R4U + 255)/256, 256>>>(bih, bhh);
    k_init_ac     <<<(BS*U + 255)/256, 256>>>(a0, c0);

    // ---- encoder + time-invariant attention precompute ----
    k_encoder<<<BS*G, 32>>>(features, enc_W, enc_b, enc_g, enc_beta);
    k_qkf<<<dim3(BS*G/96, 4), 272>>>(in_w, in_b);
    k_trkf<<<dim3((G+31)/32, (E+31)/32, BS), dim3(32, 8)>>>();
    k_agemm<<<dim3((G+63)/64, (G+63)/64, BS*H), 256>>>();
    k_expE<<<BS*H*G/8, 256>>>();

    // ---- timestep loop ----
    for (int t = 0; t < T; t++){
        k_qa   <<<BS, E>>>(in_b);
        k_ve   <<<BS*H, 384>>>();
        k_attn <<<BS*H*NTILE, 384>>>();
        k_ctx  <<<BS, 384>>>(out, t);
        k_gates<<<dim3(R4U/256, BS/8), 256>>>(text, emb, t);
        k_lstm <<<BS, U>>>(ln_g, ln_b);
        k_mlp1 <<<BS, 256>>>(b1);
        k_mlp2 <<<BS, 512>>>(b2, out, t);
    }
}

// round 5
// speedup vs baseline: 1.3831x; 1.3831x over previous
#include <cuda_runtime.h>
#include <cuda_fp16.h>

#define BS 64
#define G 360
#define V 100
#define D 32
#define U 512
#define T 15
#define VOC 5000
#define VOCP 5120
#define TD 512
#define H 8
#define E 544          // D + U
#define HD 68          // E / H
#define NEG 0.2f
#define INV_S 0.12126781251816648f   // 1/sqrt(68)
#define XDIM 1056      // E + U
#define R4U 2048       // 4*U

// ----------------------------- device scratch -----------------------------
__device__ float  g_feat[BS*G*D];
__device__ float  g_qf[(size_t)BS*G*E];
__device__ float  g_kf[(size_t)BS*G*E];
__device__ float  g_kfT[(size_t)BS*E*G];
__device__ __half g_Ah[(size_t)BS*H*G*G];     // fp16 scores
__device__ __half g_Ebuf[(size_t)BS*H*G*G];   // fp16 exp(A - rowmax)
__device__ float  g_WqaT[U*E];
__device__ float  g_Wcat[(size_t)XDIM*R4U];
__device__ float  g_bias[R4U];
__device__ float  g_W2T[256*VOCP];            // padded, zero-init tail
__device__ float  g_wpart[BS*H*G];
__device__ float  g_ctx[BS*D];
__device__ float  g_gates[BS*R4U];
__device__ float  g_a[BS*U];
__device__ float  g_c[BS*U];
__device__ float  g_h1[BS*256];
__device__ float  g_logits[BS*VOC];

__device__ __forceinline__ float sigmoidf_(float x){ return 1.f/(1.f+__expf(-x)); }
__device__ __forceinline__ float leakyf_(float x){ return x > 0.f ? x : NEG*x; }

// fast exp on the FMA pipe; ~2e-6 rel error
__device__ __forceinline__ float fexp_(float x){
    float t = x * 1.4426950408889634f;
    float r = rintf(t);
    float f = t - r;
    float p =          1.3333558e-3f;
    p = fmaf(p, f, 9.6181291e-3f);
    p = fmaf(p, f, 5.5504109e-2f);
    p = fmaf(p, f, 2.4022651e-1f);
    p = fmaf(p, f, 6.9314718e-1f);
    p = fmaf(p, f, 1.0f);
    int ei = (int)r;
    if (ei < -126) ei = -126;
    return p * __int_as_float((ei + 127) << 23);
}

// ----------------------------- one-time prep ------------------------------
__global__ void k_prep1(const float* __restrict__ in_w, const float* __restrict__ bih,
                        const float* __restrict__ bhh, const float* __restrict__ a0,
                        const float* __restrict__ c0){
    int i = blockIdx.x*256 + threadIdx.x;
    if (i < U*E){ int u = i/E, e = i - u*E; g_WqaT[i] = in_w[(size_t)e*E + D + u]; }
    if (i < R4U) g_bias[i] = bih[i] + bhh[i];
    if (i < BS*U){ g_a[i] = a0[i]; g_c[i] = c0[i]; }
}
__global__ void k_prep2(const float* __restrict__ Wih, const float* __restrict__ Whh,
                        const float* __restrict__ W2){
    int i = blockIdx.x*256 + threadIdx.x;
    if (i < E*R4U){ int x = i/R4U, r = i - x*R4U; g_Wcat[i] = Wih[(size_t)r*E + x]; }
    if (i < U*R4U){ int u = i/R4U, r = i - u*R4U; g_Wcat[(size_t)(E+u)*R4U + r] = Whh[(size_t)r*U + u]; }
    if (i < 256*VOC){ int k = i/VOC, v = i - k*VOC; g_W2T[(size_t)k*VOCP + v] = W2[(size_t)v*256 + k]; }
}

// ---------------------- encoder: feat = lrelu(LN(x@W+b)) -------------------
__global__ void k_encoder(const float* __restrict__ features, const float* __restrict__ enc_W,
                          const float* __restrict__ enc_b, const float* __restrict__ enc_g,
                          const float* __restrict__ enc_beta){
    int g = blockIdx.x;
    int tid = threadIdx.x;               // 256
    int warp = tid >> 5, lane = tid & 31;
    __shared__ float Ws[D*101];
    __shared__ float bs_[D];
    __shared__ float xw[8][V];
    for (int k = tid; k < D*V; k += 256){
        int d = k / V, v = k - d*V;
        Ws[d*101 + v] = enc_W[(size_t)g*D*V + k];
    }
    if (tid < D) bs_[tid] = enc_b[g*D + tid];
    __syncthreads();
    float gg = enc_g[lane], bb = enc_beta[lane];
    for (int b = warp; b < BS; b += 8){
        for (int v = lane; v < V; v += 32) xw[warp][v] = features[((size_t)b*G + g)*V + v];
        __syncwarp();
        const float* w = Ws + lane*101;
        float acc = bs_[lane];
        #pragma unroll 4
        for (int v = 0; v < V; v++) acc = fmaf(xw[warp][v], w[v], acc);
        float m = acc;
        #pragma unroll
        for (int o=16;o;o>>=1) m += __shfl_xor_sync(0xffffffffu, m, o);
        m *= (1.f/32.f);
        float dv = acc - m, vv = dv*dv;
        #pragma unroll
        for (int o=16;o;o>>=1) vv += __shfl_xor_sync(0xffffffffu, vv, o);
        vv *= (1.f/32.f);
        float y = dv*rsqrtf(vv+1e-5f)*gg + bb;
        g_feat[((size_t)b*G + g)*D + lane] = leakyf_(y);
        __syncwarp();
    }
}

// ---------------------- qf / kf projections (K = 32) ----------------------
__global__ void k_qkf(const float* __restrict__ in_w){
    int mat = blockIdx.y >> 1;
    int eh  = blockIdx.y & 1;
    int le  = threadIdx.x;               // 0..271
    int ebase = eh*272;
    __shared__ float Ws[272*33];
    __shared__ float fs[D];
    for (int k = le; k < 272*D; k += 272){
        int i = k >> 5, d = k & 31;
        Ws[i*33 + d] = in_w[((size_t)(mat*E + ebase + i))*E + d];
    }
    __syncthreads();
    int r0 = blockIdx.x * 96;
    for (int rr = 0; rr < 96; rr++){
        int row = r0 + rr;
        if (le < D) fs[le] = g_feat[(size_t)row*D + le];
        __syncthreads();
        float acc = 0.f;
        #pragma unroll
        for (int d = 0; d < D; d++) acc = fmaf(fs[d], Ws[le*33 + d], acc);
        if (mat == 0) g_qf[(size_t)row*E + ebase + le] = acc;
        else          g_kf[(size_t)row*E + ebase + le] = acc;
        __syncthreads();
    }
}

// ---------------------- transpose kf -> kfT[b][e][g] -----------------------
__global__ void k_trkf(){
    __shared__ float tile[32][33];
    int b = blockIdx.z;
    int g0 = blockIdx.x*32, e0 = blockIdx.y*32;
    int tx = threadIdx.x, ty = threadIdx.y;
    for (int i = ty; i < 32; i += 8){
        int g = g0 + i, e = e0 + tx;
        if (g < G && e < E) tile[i][tx] = g_kf[((size_t)b*G + g)*E + e];
    }
    __syncthreads();
    for (int i = ty; i < 32; i += 8){
        int e = e0 + i, g = g0 + tx;
        if (e < E && g < G) g_kfT[((size_t)b*E + e)*G + g] = tile[tx][i];
    }
}

// ---------------------- A[b,h,i,j] = qf.kf / sqrt(HD)  -> fp16 -------------
__global__ void k_agemm(){
    int bh = blockIdx.z; int b = bh >> 3, h = bh & 7;
    int i0 = blockIdx.y << 6, j0 = blockIdx.x << 6;
    __shared__ float Qs[HD*68];
    __shared__ float Ks[HD*68];
    int tid = threadIdx.x;               // 256
    const float* qbase = g_qf + (size_t)(b*G)*E + h*HD;
    for (int k = tid; k < 64*HD; k += 256){
        int ii = k / HD, d = k - ii*HD;
        int gi = i0 + ii;
        Qs[d*68 + ii] = (gi < G) ? qbase[(size_t)gi*E + d] : 0.f;
    }
    const float* kbase = g_kfT + ((size_t)b*E + h*HD)*G;
    for (int k = tid; k < 64*HD; k += 256){
        int d = k >> 6, jj = k & 63;
        int gj = j0 + jj;
        Ks[d*68 + jj] = (gj < G) ? kbase[(size_t)d*G + gj] : 0.f;
    }
    __syncthreads();
    int tx = tid & 15, ty = tid >> 4;
    float acc[4][4] = {};
    #pragma unroll 4
    for (int d = 0; d < HD; d++){
        float4 q4 = *(const float4*)&Qs[d*68 + (ty<<2)];
        float4 k4 = *(const float4*)&Ks[d*68 + (tx<<2)];
        float qr[4] = {q4.x,q4.y,q4.z,q4.w};
        float kr[4] = {k4.x,k4.y,k4.z,k4.w};
        #pragma unroll
        for (int r = 0; r < 4; r++)
            #pragma unroll
            for (int c = 0; c < 4; c++) acc[r][c] = fmaf(qr[r], kr[c], acc[r][c]);
    }
    #pragma unroll
    for (int r = 0; r < 4; r++){
        int i = i0 + (ty<<2) + r;
        if (i >= G) continue;
        __half* row = g_Ah + (size_t)bh*G*G + (size_t)i*G;
        #pragma unroll
        for (int c = 0; c < 4; c += 2){
            int j = j0 + (tx<<2) + c;
            if (j + 1 < G){
                *(__half2*)(row + j) = __floats2half2_rn(acc[r][c]*INV_S, acc[r][c+1]*INV_S);
            } else if (j < G){
                row[j] = __float2half(acc[r][c]*INV_S);
            }
        }
    }
}

// -------------------- E = exp(A - rowmax) fp16 -> fp16 ----------------------
__global__ void k_expE(){
    int row  = blockIdx.x*8 + (threadIdx.x >> 5);
    int lane = threadIdx.x & 31;
    const __half2* A2 = (const __half2*)(g_Ah + (size_t)row*G);
    float m = -1e30f;
    for (int p = lane; p < G/2; p += 32){
        float2 f = __half22float2(A2[p]);
        m = fmaxf(m, fmaxf(f.x, f.y));
    }
    #pragma unroll
    for (int o=16;o;o>>=1) m = fmaxf(m, __shfl_xor_sync(0xffffffffu, m, o));
    __half2* E2 = (__half2*)(g_Ebuf + (size_t)row*G);
    for (int p = lane; p < G/2; p += 32){
        float2 f = __half22float2(A2[p]);
        E2[p] = __floats2half2_rn(fexp_(f.x - m), fexp_(f.y - m));
    }
}

// ---- per-step fused attention: qa + v + e + one streaming pass over E -----
__global__ void k_att(const float* __restrict__ in_b){
    int bh = blockIdx.x; int b = bh >> 3, h = bh & 7;
    int tid = threadIdx.x;               // 384
    int warp = tid >> 5, lane = tid & 31;
    __shared__ float as_[U];
    __shared__ float qp[4][HD];
    __shared__ float qs[HD];
    __shared__ float es[G];
    __shared__ float wred[12];
    __shared__ float colsum[12][G];
    for (int u = tid; u < U; u += 384) as_[u] = g_a[b*U + u];
    __syncthreads();
    if (tid < 272){
        int d = tid % HD, part = tid / HD;
        const float* wcol = g_WqaT + h*HD + d;
        float acc = 0.f;
        int u0 = part*128;
        #pragma unroll 8
        for (int u = 0; u < 128; u++) acc = fmaf(as_[u0+u], wcol[(size_t)(u0+u)*E], acc);
        qp[part][d] = acc;
    }
    __syncthreads();
    if (tid < HD) qs[tid] = qp[0][tid]+qp[1][tid]+qp[2][tid]+qp[3][tid] + in_b[h*HD + tid];
    __syncthreads();
    float v = -1e30f;
    if (tid < G){
        const float* kcol = g_kfT + ((size_t)b*E + h*HD)*G + tid;
        float acc = 0.f;
        #pragma unroll 4
        for (int d = 0; d < HD; d++) acc = fmaf(qs[d], kcol[(size_t)d*G], acc);
        v = acc * INV_S;
    }
    float m = v;
    #pragma unroll
    for (int o=16;o;o>>=1) m = fmaxf(m, __shfl_xor_sync(0xffffffffu, m, o));
    if (lane == 0) wred[warp] = m;
    __syncthreads();
    if (tid == 0){
        float mm = wred[0];
        #pragma unroll
        for (int i = 1; i < 12; i++) mm = fmaxf(mm, wred[i]);
        wred[0] = mm;
    }
    __syncthreads();
    if (tid < G) es[tid] = fexp_(v - wred[0]);
    __syncthreads();
    float racc[12];
    #pragma unroll
    for (int k = 0; k < 12; k++) racc[k] = 0.f;
    const __half2* Eb = (const __half2*)(g_Ebuf + (size_t)bh*G*G);
    const float2* es2 = (const float2*)es;
    for (int i = warp; i < G; i += 12){
        const __half2* rowp = Eb + (size_t)i*(G/2);
        float2 f[6];
        float dot = 0.f;
        #pragma unroll
        for (int s = 0; s < 6; s++){
            int jj = lane + 32*s;
            if (jj < G/2){
                f[s] = __half22float2(rowp[jj]);
                float2 e2 = es2[jj];
                dot = fmaf(f[s].x, e2.x, dot);
                dot = fmaf(f[s].y, e2.y, dot);
            } else { f[s].x = 0.f; f[s].y = 0.f; }
        }
        #pragma unroll
        for (int o=16;o;o>>=1) dot += __shfl_xor_sync(0xffffffffu, dot, o);
        float rinv = 1.f/dot;
        #pragma unroll
        for (int s = 0; s < 6; s++){
            racc[2*s]   = fmaf(f[s].x, rinv, racc[2*s]);
            racc[2*s+1] = fmaf(f[s].y, rinv, racc[2*s+1]);
        }
    }
    #pragma unroll
    for (int s = 0; s < 6; s++){
        int jj = lane + 32*s;
        if (jj < G/2){
            colsum[warp][2*jj]   = racc[2*s];
            colsum[warp][2*jj+1] = racc[2*s+1];
        }
    }
    __syncthreads();
    if (tid < G){
        float tot = 0.f;
        #pragma unroll
        for (int w = 0; w < 12; w++) tot += colsum[w][tid];
        g_wpart[bh*G + tid] = es[tid]*tot;
    }
}

// ------------- per-step: w reduce over h + scores out + ctx ----------------
__global__ void k_ctx(float* __restrict__ out, int t){
    int b = blockIdx.x, tid = threadIdx.x;   // 384
    __shared__ float ws[G];
    __shared__ float cp[12][32];
    if (tid < G){
        float acc = 0.f;
        #pragma unroll
        for (int hh = 0; hh < H; hh++) acc += g_wpart[(b*H + hh)*G + tid];
        acc *= (1.f/(float)(H*G));
        ws[tid] = acc;
        out[(size_t)BS*T*VOC + ((size_t)b*T + t)*G + tid] = acc;
    }
    __syncthreads();
    int d = tid & 31, seg = tid >> 5;
    float acc = 0.f;
    int j0 = seg*30;
    for (int j = j0; j < j0+30; j++)
        acc = fmaf(ws[j], g_feat[((size_t)b*G + j)*D + d], acc);
    cp[seg][d] = acc;
    __syncthreads();
    if (tid < D){
        float s = 0.f;
        #pragma unroll
        for (int k = 0; k < 12; k++) s += cp[k][tid];
        g_ctx[b*D + tid] = s;
    }
}

// ------------- per-step LSTM gate GEMM: 64 x 2048 x 1056 -------------------
__global__ void k_gates(const int* __restrict__ text, const float* __restrict__ emb, int t){
    int r  = blockIdx.x*128 + threadIdx.x;   // grid.x = 16
    int b0 = blockIdx.y*8;                   // grid.y = 8
    int tid = threadIdx.x;
    __shared__ float xs[8][XDIM];
    for (int bb = 0; bb < 8; bb++){
        int b = b0 + bb;
        if (tid < D) xs[bb][tid] = g_ctx[b*D + tid];
        int tok = text[b*T + t];
        for (int x = tid; x < TD; x += 128) xs[bb][D + x] = emb[(size_t)tok*TD + x];
        for (int u = tid; u < U; u += 128)  xs[bb][E + u] = g_a[b*U + u];
    }
    __syncthreads();
    float acc[8] = {};
    const float* wp = g_Wcat + r;
    #pragma unroll 4
    for (int x = 0; x < XDIM; x++){
        float w = wp[(size_t)x*R4U];
        #pragma unroll
        for (int bb = 0; bb < 8; bb++) acc[bb] = fmaf(xs[bb][x], w, acc[bb]);
    }
    float bsv = g_bias[r];
    #pragma unroll
    for (int bb = 0; bb < 8; bb++) g_gates[(size_t)(b0+bb)*R4U + r] = acc[bb] + bsv;
}

// ------------- per-step LSTM cell + LN + MLP layer 1 (fused) ---------------
__global__ void k_lstm_mlp1(const float* __restrict__ ln_g, const float* __restrict__ ln_b,
                            const float* __restrict__ W1, const float* __restrict__ b1){
    int b = blockIdx.x, tid = threadIdx.x;   // 512
    __shared__ float sact[U];
    __shared__ float r1[16], r2[16];
    int u = tid;
    const float* gr = g_gates + (size_t)b*R4U;
    float c = sigmoidf_(gr[U+u])*g_c[b*U+u] + sigmoidf_(gr[u])*tanhf(gr[2*U+u]);
    g_c[b*U+u] = c;
    float hh = sigmoidf_(gr[3*U+u])*tanhf(c);
    float s1 = hh, s2 = hh*hh;
    #pragma unroll
    for (int o=16;o;o>>=1){ s1 += __shfl_xor_sync(0xffffffffu,s1,o); s2 += __shfl_xor_sync(0xffffffffu,s2,o); }
    int w = tid>>5, l = tid&31;
    if (l==0){ r1[w]=s1; r2[w]=s2; }
    __syncthreads();
    if (tid==0){
        float t1=0.f, t2=0.f;
        #pragma unroll
        for (int i=0;i<16;i++){ t1+=r1[i]; t2+=r2[i]; }
        r1[0]=t1; r2[0]=t2;
    }
    __syncthreads();
    float m = r1[0]*(1.f/(float)U);
    float var = r2[0]*(1.f/(float)U) - m*m;
    float a = (hh-m)*rsqrtf(var+1e-5f)*ln_g[u]+ln_b[u];
    g_a[b*U+u] = a;
    sact[u] = leakyf_(a);
    __syncthreads();
    #pragma unroll
    for (int kk = 0; kk < 16; kk++){
        int k = w*16 + kk;
        const float* wrow = W1 + (size_t)k*U;
        float acc = 0.f;
        #pragma unroll 4
        for (int uu = l; uu < U; uu += 32) acc = fmaf(sact[uu], wrow[uu], acc);
        #pragma unroll
        for (int o=16;o;o>>=1) acc += __shfl_xor_sync(0xffffffffu, acc, o);
        if (l==0){
            float y = acc + b1[k];
            g_h1[b*256+k] = leakyf_(y);
        }
    }
}

// ------------- per-step MLP layer 2 (register-blocked GEMM) ----------------
__global__ void k_mlp2(const float* __restrict__ b2){
    int v0 = blockIdx.x*64;
    int b0 = blockIdx.y*32;
    int tid = threadIdx.x;                   // 256
    int tx = tid & 31, ty = tid >> 5;
    __shared__ float h1T[256*36];
    for (int i = tid; i < 256*32; i += 256){
        int k = i & 255, bb = i >> 8;
        h1T[k*36 + bb] = g_h1[(size_t)(b0+bb)*256 + k];
    }
    __syncthreads();
    int v = v0 + tx*2;
    float acc[2][4] = {};
    const float* w2 = g_W2T + v;
    const float* hp = h1T + ty*4;
    #pragma unroll 4
    for (int k = 0; k < 256; k++){
        float2 w = *(const float2*)(w2 + (size_t)k*VOCP);
        float4 hv = *(const float4*)(hp + k*36);
        acc[0][0] = fmaf(w.x, hv.x, acc[0][0]);
        acc[0][1] = fmaf(w.x, hv.y, acc[0][1]);
        acc[0][2] = fmaf(w.x, hv.z, acc[0][2]);
        acc[0][3] = fmaf(w.x, hv.w, acc[0][3]);
        acc[1][0] = fmaf(w.y, hv.x, acc[1][0]);
        acc[1][1] = fmaf(w.y, hv.y, acc[1][1]);
        acc[1][2] = fmaf(w.y, hv.z, acc[1][2]);
        acc[1][3] = fmaf(w.y, hv.w, acc[1][3]);
    }
    float bv0 = (v < VOC)   ? b2[v]   : 0.f;
    float bv1 = (v+1 < VOC) ? b2[v+1] : 0.f;
    #pragma unroll
    for (int bb = 0; bb < 4; bb++){
        int b = b0 + ty*4 + bb;
        if (v < VOC)   g_logits[(size_t)b*VOC + v]   = acc[0][bb] + bv0;
        if (v+1 < VOC) g_logits[(size_t)b*VOC + v+1] = acc[1][bb] + bv1;
    }
}

// ------------- per-step softmax over VOC -----------------------------------
__global__ void k_soft(float* __restrict__ out, int t){
    int b = blockIdx.x, tid = threadIdx.x;   // 512
    __shared__ float buf[VOC];
    __shared__ float red[16];
    float m = -1e30f;
    for (int v = tid; v < VOC; v += 512){
        float x = g_logits[(size_t)b*VOC+v];
        buf[v] = x;
        m = fmaxf(m, x);
    }
    #pragma unroll
    for (int o=16;o;o>>=1) m = fmaxf(m, __shfl_xor_sync(0xffffffffu,m,o));
    if ((tid&31)==0) red[tid>>5]=m;
    __syncthreads();
    if (tid==0){ float mm=red[0]; for(int i=1;i<16;i++) mm=fmaxf(mm,red[i]); red[0]=mm; }
    __syncthreads();
    m = red[0];
    __syncthreads();
    float s = 0.f;
    for (int v = tid; v < VOC; v += 512){
        float e = fexp_(buf[v]-m);
        buf[v] = e;
        s += e;
    }
    #pragma unroll
    for (int o=16;o;o>>=1) s += __shfl_xor_sync(0xffffffffu,s,o);
    if ((tid&31)==0) red[tid>>5]=s;
    __syncthreads();
    if (tid==0){ float ss=0.f; for(int i=0;i<16;i++) ss+=red[i]; red[0]=1.f/ss; }
    __syncthreads();
    float inv = red[0];
    float* orow = out + ((size_t)b*T + t)*VOC;
    for (int v = tid; v < VOC; v += 512) orow[v] = buf[v]*inv;
}

// ---------------------------------------------------------------------------
extern "C" void kernel_launch(void* const* d_in, const int* in_sizes, int n_in,
                              void* d_out, int out_size){
    const float* features = (const float*)d_in[0];
    const int*   text     = (const int*)  d_in[1];
    const float* a0       = (const float*)d_in[2];
    const float* c0       = (const float*)d_in[3];
    const float* enc_W    = (const float*)d_in[4];
    const float* enc_b    = (const float*)d_in[5];
    const float* enc_g    = (const float*)d_in[6];
    const float* enc_beta = (const float*)d_in[7];
    const float* emb      = (const float*)d_in[8];
    const float* in_w     = (const float*)d_in[9];
    const float* in_b     = (const float*)d_in[10];
    const float* Wih      = (const float*)d_in[11];
    const float* Whh      = (const float*)d_in[12];
    const float* bih      = (const float*)d_in[13];
    const float* bhh      = (const float*)d_in[14];
    const float* ln_g     = (const float*)d_in[15];
    const float* ln_b     = (const float*)d_in[16];
    const float* W1       = (const float*)d_in[17];
    const float* b1       = (const float*)d_in[18];
    const float* W2       = (const float*)d_in[19];
    const float* b2       = (const float*)d_in[20];
    float* out = (float*)d_out;
    (void)in_sizes; (void)n_in; (void)out_size;

    k_prep1<<<(U*E + 255)/256, 256>>>(in_w, bih, bhh, a0, c0);
    // FIX: grid must cover 256*VOC (largest of the three fills), was E*R4U.
    k_prep2<<<(256*VOC + 255)/256, 256>>>(Wih, Whh, W2);
    k_encoder<<<G, 256>>>(features, enc_W, enc_b, enc_g, enc_beta);
    k_qkf<<<dim3(BS*G/96, 4), 272>>>(in_w);
    k_trkf<<<dim3((G+31)/32, (E+31)/32, BS), dim3(32, 8)>>>();
    k_agemm<<<dim3(6, 6, BS*H), 256>>>();                             // launch 5 (profiled)
    k_expE<<<BS*H*G/8, 256>>>();

    for (int t = 0; t < T; t++){
        k_att      <<<BS*H, 384>>>(in_b);
        k_ctx      <<<BS, 384>>>(out, t);
        k_gates    <<<dim3(16, 8), 128>>>(text, emb, t);
        k_lstm_mlp1<<<BS, 512>>>(ln_g, ln_b, W1, b1);
        k_mlp2     <<<dim3((VOC+63)/64, 2), 256>>>(b2);
        k_soft     <<<BS, 512>>>(out, t);
    }
}